// round 1
// baseline (speedup 1.0000x reference)
#include <cuda_runtime.h>
#include <math.h>

// ---------------- Problem constants ----------------
#define DIMV    512
#define HEADS   16
#define DHEAD   32
#define WINSZ   8
#define NWIN    512          // B * RH * RW = 8*8*8
#define NTOK    65           // 1 region token + 64 local tokens
#define NROWS   (NWIN*NTOK)  // 33280
#define NB      8
#define DEPTH   4
#define QSCALE  0.17677669529663687f  // 32^-0.5
#define LOCAL_ELEMS (8*64*64*512)     // 16,777,216

// ---------------- Scratch (device globals; no allocs allowed) ----------------
__device__ __align__(16) float g_xw  [NROWS*DIMV];       // token stream, windowed layout
__device__ __align__(16) float g_h   [NROWS*DIMV];       // LN output
__device__ __align__(16) float g_qkv [NROWS*3*DIMV];
__device__ __align__(16) float g_o   [NROWS*DIMV];       // attention output
__device__ __align__(16) float g_m1  [NROWS*4*DIMV];     // MLP hidden
__device__ __align__(16) float g_bias[HEADS*NTOK*NTOK];  // rel-pos bias, padded
__device__ __align__(16) float g_xr  [NWIN*DIMV];        // region tokens gathered
__device__ __align__(16) float g_hr  [NWIN*DIMV];
__device__ __align__(16) float g_qkvr[NWIN*3*DIMV];
__device__ __align__(16) float g_or  [NWIN*DIMV];

// ---------------- Pack: inputs -> windowed layout ----------------
__global__ void pack_kernel(const float* __restrict__ local_t, const float* __restrict__ region_t) {
    int idx = blockIdx.x * blockDim.x + threadIdx.x;
    if (idx >= NROWS*DIMV) return;
    int d   = idx & 511;
    int row = idx >> 9;
    int win = row / NTOK, t = row - win*NTOK;
    float v;
    if (t == 0) {
        v = region_t[win*DIMV + d];
    } else {
        int a  = t - 1;
        int p1 = a >> 3, p2 = a & 7;
        int b  = win >> 6, rh = (win >> 3) & 7, rw = win & 7;
        v = local_t[(((b*64) + (rh*8 + p1))*64 + (rw*8 + p2))*DIMV + d];
    }
    g_xw[idx] = v;
}

// ---------------- Unpack: windowed layout -> output (local, then region) ----------------
__global__ void unpack_kernel(float* __restrict__ out) {
    int idx = blockIdx.x * blockDim.x + threadIdx.x;
    if (idx >= NROWS*DIMV) return;
    if (idx < LOCAL_ELEMS) {
        int d    = idx & 511;
        int p    = idx >> 9;           // token index 0..32767
        int col  = p & 63;
        int rowi = (p >> 6) & 63;
        int b    = p >> 12;
        int rh = rowi >> 3, p1 = rowi & 7;
        int rw = col  >> 3, p2 = col  & 7;
        int win = b*64 + rh*8 + rw;
        int t   = 1 + p1*8 + p2;
        out[idx] = g_xw[(win*NTOK + t)*DIMV + d];
    } else {
        int r = idx - LOCAL_ELEMS;
        int w = r >> 9, d = r & 511;
        out[idx] = g_xw[(w*NTOK)*DIMV + d];
    }
}

// ---------------- Relative position bias (computed once) ----------------
__global__ void bias_kernel(const float* __restrict__ emb) {
    int idx = blockIdx.x * blockDim.x + threadIdx.x;
    if (idx >= HEADS*NTOK*NTOK) return;
    int h = idx / (NTOK*NTOK);
    int r = idx - h*NTOK*NTOK;
    int i = r / NTOK, j = r - i*NTOK;
    float v = 0.f;
    if (i > 0 && j > 0) {
        int a = i - 1, b = j - 1;
        int r0 = (a >> 3) - (b >> 3) + 7;   // gx = p1
        int r1 = (a & 7) - (b & 7) + 7;     // gy = p2
        v = emb[(r0 + r1*15)*HEADS + h];
    }
    g_bias[idx] = v;
}

// ---------------- Region gather / scatter (slot 0 of each window) ----------------
__global__ void gather_region() {
    int idx = blockIdx.x * blockDim.x + threadIdx.x;
    if (idx >= NWIN*DIMV) return;
    int w = idx >> 9, d = idx & 511;
    g_xr[idx] = g_xw[(w*NTOK)*DIMV + d];
}
__global__ void scatter_region() {
    int idx = blockIdx.x * blockDim.x + threadIdx.x;
    if (idx >= NWIN*DIMV) return;
    int w = idx >> 9, d = idx & 511;
    g_xw[(w*NTOK)*DIMV + d] = g_xr[idx];
}

// ---------------- LayerNorm (one 128-thread block per 512-wide row) ----------------
__global__ void ln_kernel(const float* __restrict__ x, const float* __restrict__ g,
                          const float* __restrict__ b, float* __restrict__ y) {
    int row = blockIdx.x;
    int t   = threadIdx.x;  // 128
    const float4* xv = (const float4*)(x + (size_t)row*DIMV);
    float4 v = xv[t];
    float s  = v.x + v.y + v.z + v.w;
    float s2 = v.x*v.x + v.y*v.y + v.z*v.z + v.w*v.w;
    #pragma unroll
    for (int off = 16; off; off >>= 1) {
        s  += __shfl_xor_sync(0xffffffffu, s,  off);
        s2 += __shfl_xor_sync(0xffffffffu, s2, off);
    }
    __shared__ float sh[8];
    int wid = t >> 5, lane = t & 31;
    if (lane == 0) { sh[wid] = s; sh[4 + wid] = s2; }
    __syncthreads();
    float st  = sh[0] + sh[1] + sh[2] + sh[3];
    float s2t = sh[4] + sh[5] + sh[6] + sh[7];
    float mean = st * (1.f/512.f);
    float var  = s2t * (1.f/512.f) - mean*mean;
    float rstd = rsqrtf(var + 1e-3f);
    float4 gg = ((const float4*)g)[t];
    float4 bb = ((const float4*)b)[t];
    float4 o;
    o.x = (v.x - mean)*rstd*gg.x + bb.x;
    o.y = (v.y - mean)*rstd*gg.y + bb.y;
    o.z = (v.z - mean)*rstd*gg.z + bb.z;
    o.w = (v.w - mean)*rstd*gg.w + bb.w;
    ((float4*)(y + (size_t)row*DIMV))[t] = o;
}

// ---------------- SGEMM: C = A@B (+ epilogues). 128x128x16 tile, 8x8/thread ----------------
// epi: 0 -> C = AB
//      1 -> C = AB + bias + C   (residual in place)
//      2 -> C = gelu(AB + bias) (exact erf gelu)
__device__ __forceinline__ float gelu_exact(float x) {
    return 0.5f * x * (1.0f + erff(x * 0.70710678118654752f));
}

__global__ __launch_bounds__(256) void sgemm(const float* __restrict__ A, const float* __restrict__ B,
                                             const float* __restrict__ bias, float* __restrict__ C,
                                             int M, int N, int K, int epi) {
    __shared__ float As[16][128];
    __shared__ float Bs[16][128];
    const int bm = blockIdx.y * 128;
    const int bn = blockIdx.x * 128;
    const int tid = threadIdx.x;
    const int tr = (tid >> 4) << 3;
    const int tc = (tid & 15) << 3;
    const int arow = tid >> 2, acol = (tid & 3) << 2;
    const int brow = tid >> 5, bcol = (tid & 31) << 2;

    float acc[8][8];
    #pragma unroll
    for (int i = 0; i < 8; i++)
        #pragma unroll
        for (int j = 0; j < 8; j++) acc[i][j] = 0.f;

    for (int k0 = 0; k0 < K; k0 += 16) {
        float4 a0 = *(const float4*)&A[(size_t)(bm + arow)      * K + k0 + acol];
        float4 a1 = *(const float4*)&A[(size_t)(bm + arow + 64) * K + k0 + acol];
        As[acol+0][arow]    = a0.x; As[acol+1][arow]    = a0.y;
        As[acol+2][arow]    = a0.z; As[acol+3][arow]    = a0.w;
        As[acol+0][arow+64] = a1.x; As[acol+1][arow+64] = a1.y;
        As[acol+2][arow+64] = a1.z; As[acol+3][arow+64] = a1.w;
        float4 b0 = *(const float4*)&B[(size_t)(k0 + brow)     * N + bn + bcol];
        float4 b1 = *(const float4*)&B[(size_t)(k0 + brow + 8) * N + bn + bcol];
        *(float4*)&Bs[brow][bcol]     = b0;
        *(float4*)&Bs[brow + 8][bcol] = b1;
        __syncthreads();
        #pragma unroll
        for (int kk = 0; kk < 16; kk++) {
            float4 av0 = *(const float4*)&As[kk][tr];
            float4 av1 = *(const float4*)&As[kk][tr + 4];
            float4 bv0 = *(const float4*)&Bs[kk][tc];
            float4 bv1 = *(const float4*)&Bs[kk][tc + 4];
            float ar[8] = {av0.x, av0.y, av0.z, av0.w, av1.x, av1.y, av1.z, av1.w};
            float br[8] = {bv0.x, bv0.y, bv0.z, bv0.w, bv1.x, bv1.y, bv1.z, bv1.w};
            #pragma unroll
            for (int i = 0; i < 8; i++)
                #pragma unroll
                for (int j = 0; j < 8; j++) acc[i][j] += ar[i] * br[j];
        }
        __syncthreads();
    }

    #pragma unroll
    for (int i = 0; i < 8; i++) {
        size_t r = (size_t)(bm + tr + i);
        #pragma unroll
        for (int j = 0; j < 8; j += 4) {
            int c = bn + tc + j;
            float4 o;
            o.x = acc[i][j+0]; o.y = acc[i][j+1]; o.z = acc[i][j+2]; o.w = acc[i][j+3];
            if (epi == 1) {
                float4 bi  = *(const float4*)&bias[c];
                float4 res = *(const float4*)&C[r*N + c];
                o.x += bi.x + res.x; o.y += bi.y + res.y;
                o.z += bi.z + res.z; o.w += bi.w + res.w;
            } else if (epi == 2) {
                float4 bi = *(const float4*)&bias[c];
                o.x = gelu_exact(o.x + bi.x); o.y = gelu_exact(o.y + bi.y);
                o.z = gelu_exact(o.z + bi.z); o.w = gelu_exact(o.w + bi.w);
            }
            *(float4*)&C[r*N + c] = o;
        }
    }
}

// ---------------- Attention: one block per (group, head). NT tokens, head dim 32 ----------------
template<int NT>
__global__ __launch_bounds__(256) void attn_kernel(const float* __restrict__ qkv,
                                                   const float* __restrict__ biasTab,
                                                   float* __restrict__ o) {
    __shared__ float qs[NT][33];
    __shared__ float ks[NT][33];
    __shared__ float vs[NT][33];
    __shared__ float ss[NT][NT + 1];
    const int grp = blockIdx.x;
    const int h   = blockIdx.y;
    const int base = grp * NT;
    const int tid = threadIdx.x;

    // load q,k,v (q pre-scaled)
    for (int p = tid; p < NT * DHEAD; p += 256) {
        int i = p >> 5, d = p & 31;
        const float* row = qkv + (size_t)(base + i) * (3*DIMV) + h*DHEAD + d;
        qs[i][d] = row[0] * QSCALE;
        ks[i][d] = row[DIMV];
        vs[i][d] = row[2*DIMV];
    }
    __syncthreads();

    // sim = q @ k^T (+ bias)
    for (int p = tid; p < NT * NT; p += 256) {
        int i = p / NT, j = p - i*NT;
        float acc = 0.f;
        #pragma unroll
        for (int d = 0; d < 32; d++) acc += qs[i][d] * ks[j][d];
        if (biasTab) acc += biasTab[(h*NT + i)*NT + j];
        ss[i][j] = acc;
    }
    __syncthreads();

    // softmax per row (warp per row)
    int wid = tid >> 5, lane = tid & 31;
    for (int i = wid; i < NT; i += 8) {
        float m = -1e30f;
        for (int j = lane; j < NT; j += 32) m = fmaxf(m, ss[i][j]);
        #pragma unroll
        for (int off = 16; off; off >>= 1) m = fmaxf(m, __shfl_xor_sync(0xffffffffu, m, off));
        float sum = 0.f;
        for (int j = lane; j < NT; j += 32) { float e = __expf(ss[i][j] - m); ss[i][j] = e; sum += e; }
        #pragma unroll
        for (int off = 16; off; off >>= 1) sum += __shfl_xor_sync(0xffffffffu, sum, off);
        float inv = 1.f / sum;
        for (int j = lane; j < NT; j += 32) ss[i][j] *= inv;
    }
    __syncthreads();

    // out = attn @ v
    for (int p = tid; p < NT * DHEAD; p += 256) {
        int i = p >> 5, d = p & 31;
        float acc = 0.f;
        #pragma unroll 5
        for (int j = 0; j < NT; j++) acc += ss[i][j] * vs[j][d];
        o[(size_t)(base + i) * DIMV + h*DHEAD + d] = acc;
    }
}

// ---------------- Host driver ----------------
extern "C" void kernel_launch(void* const* d_in, const int* in_sizes, int n_in,
                              void* d_out, int out_size) {
    const float* local_t  = (const float*)d_in[0];
    const float* region_t = (const float*)d_in[1];
    const float* emb      = (const float*)d_in[2];
    const float* attn_g   = (const float*)d_in[3];
    const float* attn_b   = (const float*)d_in[4];
    const float* wqkv     = (const float*)d_in[5];
    const float* wout     = (const float*)d_in[6];
    const float* bout     = (const float*)d_in[7];
    const float* mlp_g    = (const float*)d_in[8];
    const float* mlp_b    = (const float*)d_in[9];
    const float* w1       = (const float*)d_in[10];
    const float* b1       = (const float*)d_in[11];
    const float* w2       = (const float*)d_in[12];
    const float* b2       = (const float*)d_in[13];
    float* out = (float*)d_out;

    float *xw, *h, *qkv, *o, *m1, *bias, *xr, *hr, *qkvr, *orr;
    cudaGetSymbolAddress((void**)&xw,   g_xw);
    cudaGetSymbolAddress((void**)&h,    g_h);
    cudaGetSymbolAddress((void**)&qkv,  g_qkv);
    cudaGetSymbolAddress((void**)&o,    g_o);
    cudaGetSymbolAddress((void**)&m1,   g_m1);
    cudaGetSymbolAddress((void**)&bias, g_bias);
    cudaGetSymbolAddress((void**)&xr,   g_xr);
    cudaGetSymbolAddress((void**)&hr,   g_hr);
    cudaGetSymbolAddress((void**)&qkvr, g_qkvr);
    cudaGetSymbolAddress((void**)&orr,  g_or);

    pack_kernel<<<(NROWS*DIMV + 255)/256, 256>>>(local_t, region_t);
    bias_kernel<<<(HEADS*NTOK*NTOK + 255)/256, 256>>>(emb);

    for (int l = 0; l < DEPTH; l++) {
        const float* Wqkv = wqkv + (size_t)l*DIMV*3*DIMV;
        const float* Wout = wout + (size_t)l*DIMV*DIMV;
        const float* Bout = bout + (size_t)l*DIMV;
        const float* W1   = w1   + (size_t)l*DIMV*4*DIMV;
        const float* B1   = b1   + (size_t)l*4*DIMV;
        const float* W2   = w2   + (size_t)l*4*DIMV*DIMV;
        const float* B2   = b2   + (size_t)l*DIMV;
        const float* Ag   = attn_g + (size_t)l*DIMV;
        const float* Ab   = attn_b + (size_t)l*DIMV;
        const float* Mg   = mlp_g  + (size_t)l*DIMV;
        const float* Mb   = mlp_b  + (size_t)l*DIMV;

        // ---- region self-attention ----
        gather_region<<<(NWIN*DIMV + 255)/256, 256>>>();
        ln_kernel<<<NWIN, 128>>>(xr, Ag, Ab, hr);
        sgemm<<<dim3(3*DIMV/128, NWIN/128), 256>>>(hr, Wqkv, nullptr, qkvr, NWIN, 3*DIMV, DIMV, 0);
        attn_kernel<64><<<dim3(NB, HEADS), 256>>>(qkvr, nullptr, orr);
        sgemm<<<dim3(DIMV/128, NWIN/128), 256>>>(orr, Wout, Bout, xr, NWIN, DIMV, DIMV, 1);
        scatter_region<<<(NWIN*DIMV + 255)/256, 256>>>();

        // ---- window attention (all 65 slots, region token included) ----
        ln_kernel<<<NROWS, 128>>>(xw, Ag, Ab, h);
        sgemm<<<dim3(3*DIMV/128, NROWS/128), 256>>>(h, Wqkv, nullptr, qkv, NROWS, 3*DIMV, DIMV, 0);
        attn_kernel<NTOK><<<dim3(NWIN, HEADS), 256>>>(qkv, bias, o);
        sgemm<<<dim3(DIMV/128, NROWS/128), 256>>>(o, Wout, Bout, xw, NROWS, DIMV, DIMV, 1);

        // ---- MLP ----
        ln_kernel<<<NROWS, 128>>>(xw, Mg, Mb, h);
        sgemm<<<dim3(4*DIMV/128, NROWS/128), 256>>>(h, W1, B1, m1, NROWS, 4*DIMV, DIMV, 2);
        sgemm<<<dim3(DIMV/128, NROWS/128), 256>>>(m1, W2, B2, xw, NROWS, DIMV, 4*DIMV, 1);
    }

    unpack_kernel<<<(NROWS*DIMV + 255)/256, 256>>>(out);
}

// round 3
// speedup vs baseline: 1.9638x; 1.9638x over previous
#include <cuda_runtime.h>
#include <cuda_bf16.h>
#include <math.h>
#include <stdint.h>

// ---------------- Problem constants ----------------
#define DIMV    512
#define HEADS   16
#define DHEAD   32
#define NWIN    512          // B * RH * RW
#define NTOK    65           // 1 region + 64 local
#define NROWS   (NWIN*NTOK)  // 33280 (= 260 * 128)
#define NB      8
#define DEPTH   4
#define QSCALE  0.17677669529663687f
#define LOCAL_ELEMS (8*64*64*512)

// ---------------- helpers ----------------
__device__ __forceinline__ uint32_t smem_to_u32(const void* p) {
    uint32_t a;
    asm("{ .reg .u64 t; cvta.to.shared.u64 t, %1; cvt.u32.u64 %0, t; }" : "=r"(a) : "l"(p));
    return a;
}
__device__ __forceinline__ void cp16(uint32_t dst, const void* src) {
    asm volatile("cp.async.cg.shared.global [%0], [%1], 16;\n" :: "r"(dst), "l"(src));
}
__device__ __forceinline__ void cp_commit() { asm volatile("cp.async.commit_group;\n" ::: "memory"); }

__device__ __forceinline__ void split_bf16(float x, __nv_bfloat16& h, __nv_bfloat16& l) {
    h = __float2bfloat16(x);
    l = __float2bfloat16(x - __bfloat162float(h));
}
__device__ __forceinline__ float gelu_exact(float x) {
    return 0.5f * x * (1.0f + erff(x * 0.70710678118654752f));
}

// ================= Scratch (device globals) =================
// Activations with hi/lo split stored as [row][2K]: hi in [0,K), lo in [K,2K)
__device__ __align__(16) float         g_xw  [NROWS*DIMV];
__device__ __align__(16) __nv_bfloat16 g_h   [NROWS*2*DIMV];
__device__ __align__(16) float         g_qkv [NROWS*3*DIMV];
__device__ __align__(16) __nv_bfloat16 g_o   [NROWS*2*DIMV];
__device__ __align__(16) __nv_bfloat16 g_m1  [NROWS*2*4*DIMV];
__device__ __align__(16) float         g_bias[HEADS*NTOK*NTOK];
__device__ __align__(16) float         g_xr  [NWIN*DIMV];
__device__ __align__(16) __nv_bfloat16 g_hr  [NWIN*2*DIMV];
__device__ __align__(16) float         g_qkvr[NWIN*3*DIMV];
__device__ __align__(16) __nv_bfloat16 g_or  [NWIN*2*DIMV];
// Weights transposed+split: [N][2K] (hi [0,K), lo [K,2K))
__device__ __align__(16) __nv_bfloat16 g_Wqkv[DEPTH*3*DIMV*2*DIMV];
__device__ __align__(16) __nv_bfloat16 g_Wout[DEPTH*DIMV*2*DIMV];
__device__ __align__(16) __nv_bfloat16 g_W1  [DEPTH*4*DIMV*2*DIMV];
__device__ __align__(16) __nv_bfloat16 g_W2  [DEPTH*DIMV*2*4*DIMV];

// ================= small kernels =================
__global__ void pack_kernel(const float* __restrict__ local_t, const float* __restrict__ region_t) {
    int idx = blockIdx.x * blockDim.x + threadIdx.x;
    if (idx >= NROWS*DIMV) return;
    int d = idx & 511, row = idx >> 9;
    int win = row / NTOK, t = row - win*NTOK;
    float v;
    if (t == 0) v = region_t[win*DIMV + d];
    else {
        int a = t - 1, p1 = a >> 3, p2 = a & 7;
        int b = win >> 6, rh = (win >> 3) & 7, rw = win & 7;
        v = local_t[(((b*64) + (rh*8 + p1))*64 + (rw*8 + p2))*DIMV + d];
    }
    g_xw[idx] = v;
}

__global__ void unpack_kernel(float* __restrict__ out) {
    int idx = blockIdx.x * blockDim.x + threadIdx.x;
    if (idx >= NROWS*DIMV) return;
    if (idx < LOCAL_ELEMS) {
        int d = idx & 511, p = idx >> 9;
        int col = p & 63, rowi = (p >> 6) & 63, b = p >> 12;
        int rh = rowi >> 3, p1 = rowi & 7, rw = col >> 3, p2 = col & 7;
        int win = b*64 + rh*8 + rw, t = 1 + p1*8 + p2;
        out[idx] = g_xw[(win*NTOK + t)*DIMV + d];
    } else {
        int r = idx - LOCAL_ELEMS, w = r >> 9, d = r & 511;
        out[idx] = g_xw[(w*NTOK)*DIMV + d];
    }
}

__global__ void bias_kernel(const float* __restrict__ emb) {
    int idx = blockIdx.x * blockDim.x + threadIdx.x;
    if (idx >= HEADS*NTOK*NTOK) return;
    int h = idx / (NTOK*NTOK);
    int r = idx - h*NTOK*NTOK;
    int i = r / NTOK, j = r - i*NTOK;
    float v = 0.f;
    if (i > 0 && j > 0) {
        int a = i - 1, b = j - 1;
        int r0 = (a >> 3) - (b >> 3) + 7;
        int r1 = (a & 7) - (b & 7) + 7;
        v = emb[(r0 + r1*15)*HEADS + h];
    }
    g_bias[idx] = v;
}

__global__ void gather_region() {
    int idx = blockIdx.x * blockDim.x + threadIdx.x;
    if (idx >= NWIN*DIMV) return;
    int w = idx >> 9, d = idx & 511;
    g_xr[idx] = g_xw[(w*NTOK)*DIMV + d];
}
__global__ void scatter_region() {
    int idx = blockIdx.x * blockDim.x + threadIdx.x;
    if (idx >= NWIN*DIMV) return;
    int w = idx >> 9, d = idx & 511;
    g_xw[(w*NTOK)*DIMV + d] = g_xr[idx];
}

// transpose + split weights: W[K,N] fp32 -> out[n][2K] bf16 (hi then lo)
__global__ void wsplit(const float* __restrict__ W, __nv_bfloat16* __restrict__ OutW, int K, int N) {
    int idx = blockIdx.x * blockDim.x + threadIdx.x;
    if (idx >= K*N) return;
    int n = idx / K, k = idx - n*K;
    float v = W[(size_t)k*N + n];
    __nv_bfloat16 h, l; split_bf16(v, h, l);
    OutW[(size_t)n*2*K + k]     = h;
    OutW[(size_t)n*2*K + K + k] = l;
}

// LayerNorm: 128 threads per 512-wide row, emits split bf16 into [row][1024]
__global__ void ln_kernel(const float* __restrict__ x, const float* __restrict__ g,
                          const float* __restrict__ b, __nv_bfloat16* __restrict__ y) {
    int row = blockIdx.x;
    int t = threadIdx.x;
    const float4* xv = (const float4*)(x + (size_t)row*DIMV);
    float4 v = xv[t];
    float s  = v.x + v.y + v.z + v.w;
    float s2 = v.x*v.x + v.y*v.y + v.z*v.z + v.w*v.w;
    #pragma unroll
    for (int off = 16; off; off >>= 1) {
        s  += __shfl_xor_sync(0xffffffffu, s,  off);
        s2 += __shfl_xor_sync(0xffffffffu, s2, off);
    }
    __shared__ float sh[8];
    int wid = t >> 5, lane = t & 31;
    if (lane == 0) { sh[wid] = s; sh[4 + wid] = s2; }
    __syncthreads();
    float st  = sh[0] + sh[1] + sh[2] + sh[3];
    float s2t = sh[4] + sh[5] + sh[6] + sh[7];
    float mean = st * (1.f/512.f);
    float var  = s2t * (1.f/512.f) - mean*mean;
    float rstd = rsqrtf(var + 1e-3f);
    float4 gg = ((const float4*)g)[t];
    float4 bb = ((const float4*)b)[t];
    float o0 = (v.x - mean)*rstd*gg.x + bb.x;
    float o1 = (v.y - mean)*rstd*gg.y + bb.y;
    float o2 = (v.z - mean)*rstd*gg.z + bb.z;
    float o3 = (v.w - mean)*rstd*gg.w + bb.w;
    __nv_bfloat16 h0,h1,h2,h3,l0,l1,l2,l3;
    split_bf16(o0,h0,l0); split_bf16(o1,h1,l1); split_bf16(o2,h2,l2); split_bf16(o3,h3,l3);
    __nv_bfloat162* pH = (__nv_bfloat162*)(y + (size_t)row*1024 + 4*t);
    __nv_bfloat162* pL = (__nv_bfloat162*)(y + (size_t)row*1024 + 512 + 4*t);
    __nv_bfloat162 a0; a0.x = h0; a0.y = h1;
    __nv_bfloat162 a1; a1.x = h2; a1.y = h3;
    __nv_bfloat162 c0; c0.x = l0; c0.y = l1;
    __nv_bfloat162 c1; c1.x = l2; c1.y = l3;
    pH[0] = a0; pH[1] = a1;
    pL[0] = c0; pL[1] = c1;
}

// ================= Attention (fp32 in smem) =================
template<int NT>
__global__ __launch_bounds__(256) void attn_kernel(const float* __restrict__ qkv,
                                                   const float* __restrict__ biasTab,
                                                   __nv_bfloat16* __restrict__ o) {
    __shared__ float qs[NT][33];
    __shared__ float ks[NT][33];
    __shared__ float vs[NT][33];
    __shared__ float ss[NT][NT + 1];
    const int grp = blockIdx.x;
    const int h   = blockIdx.y;
    const int base = grp * NT;
    const int tid = threadIdx.x;

    for (int p = tid; p < NT * DHEAD; p += 256) {
        int i = p >> 5, d = p & 31;
        const float* row = qkv + (size_t)(base + i) * (3*DIMV) + h*DHEAD + d;
        qs[i][d] = row[0] * QSCALE;
        ks[i][d] = row[DIMV];
        vs[i][d] = row[2*DIMV];
    }
    __syncthreads();

    for (int p = tid; p < NT * NT; p += 256) {
        int i = p / NT, j = p - i*NT;
        float acc = 0.f;
        #pragma unroll
        for (int d = 0; d < 32; d++) acc += qs[i][d] * ks[j][d];
        if (biasTab) acc += biasTab[(h*NT + i)*NT + j];
        ss[i][j] = acc;
    }
    __syncthreads();

    int wid = tid >> 5, lane = tid & 31;
    for (int i = wid; i < NT; i += 8) {
        float m = -1e30f;
        for (int j = lane; j < NT; j += 32) m = fmaxf(m, ss[i][j]);
        #pragma unroll
        for (int off = 16; off; off >>= 1) m = fmaxf(m, __shfl_xor_sync(0xffffffffu, m, off));
        float sum = 0.f;
        for (int j = lane; j < NT; j += 32) { float e = __expf(ss[i][j] - m); ss[i][j] = e; sum += e; }
        #pragma unroll
        for (int off = 16; off; off >>= 1) sum += __shfl_xor_sync(0xffffffffu, sum, off);
        float inv = 1.f / sum;
        for (int j = lane; j < NT; j += 32) ss[i][j] *= inv;
    }
    __syncthreads();

    for (int p = tid; p < NT * DHEAD; p += 256) {
        int i = p >> 5, d = p & 31;
        float acc = 0.f;
        #pragma unroll 5
        for (int j = 0; j < NT; j++) acc += ss[i][j] * vs[j][d];
        __nv_bfloat16 hh, ll; split_bf16(acc, hh, ll);
        size_t ob = (size_t)(base + i) * 1024 + h*DHEAD + d;
        o[ob] = hh; o[ob + 512] = ll;
    }
}

// ================= bf16 split GEMM via mma.sync =================
// C[M,N] = sum_k A[m,k]*B[n,k] with fp32-level accuracy via 3-term bf16 split:
//   AhBh + AhBl + AlBh, where A,B stored as [row][2K] (hi|lo).
// CTA tile 128x128, BK=32, 4-stage cp.async, 8 warps of 64x32 (m16n8k16 atoms).
#define BM 128
#define BN 128
#define BK 32
#define NSTG 4
#define ROWB 80                         // padded smem row bytes (64B data + 16B pad)
#define STG_BYTES ((BM + BN) * ROWB)    // 20480
#define SMEM_GEMM (NSTG * STG_BYTES)    // 81920

__global__ __launch_bounds__(256, 2) void gemm_mma(
    const __nv_bfloat16* __restrict__ A, const __nv_bfloat16* __restrict__ B,
    const float* __restrict__ bias, float* __restrict__ C,
    __nv_bfloat16* __restrict__ O, int N, int K, int epi)
{
    extern __shared__ char smem[];
    const uint32_t sb = smem_to_u32(smem);
    const int tid = threadIdx.x;
    const int bm = blockIdx.y * BM;
    const int bn = blockIdx.x * BN;
    const int lda = 2*K;
    const int cpt = K / BK;
    const int total = 3 * cpt;

    const int wid = tid >> 5, lane = tid & 31;
    const int wm = wid & 1, wn = wid >> 1;     // warp grid 2(M) x 4(N)

    float acc[4][4][4];
    #pragma unroll
    for (int mi = 0; mi < 4; mi++)
        #pragma unroll
        for (int ni = 0; ni < 4; ni++)
            #pragma unroll
            for (int r = 0; r < 4; r++) acc[mi][ni][r] = 0.f;

    // chunk loader
    auto load_chunk = [&](int c) {
        int t  = c / cpt, kk = c - t*cpt;
        int a_col = ((t == 2) ? K : 0) + kk*BK;
        int b_col = ((t == 1) ? K : 0) + kk*BK;
        uint32_t stA = sb + (c % NSTG) * STG_BYTES;
        uint32_t stB = stA + BM * ROWB;
        #pragma unroll
        for (int i = 0; i < 2; i++) {
            int s = tid + i*256;        // 512 segments: 128 rows x 4
            int row = s >> 2, seg = s & 3;
            cp16(stA + row*ROWB + seg*16, A + (size_t)(bm + row)*lda + a_col + seg*8);
            cp16(stB + row*ROWB + seg*16, B + (size_t)(bn + row)*lda + b_col + seg*8);
        }
        cp_commit();
    };

    load_chunk(0); load_chunk(1); load_chunk(2);

    for (int c = 0; c < total; c++) {
        if (c <= total - 3)      asm volatile("cp.async.wait_group 2;\n" ::: "memory");
        else if (c == total - 2) asm volatile("cp.async.wait_group 1;\n" ::: "memory");
        else                     asm volatile("cp.async.wait_group 0;\n" ::: "memory");
        __syncthreads();
        if (c + 3 < total) load_chunk(c + 3);

        uint32_t stA = sb + (c % NSTG) * STG_BYTES;
        uint32_t stB = stA + BM * ROWB;
        #pragma unroll
        for (int ks = 0; ks < 2; ks++) {
            uint32_t a[4][4];
            #pragma unroll
            for (int mi = 0; mi < 4; mi++) {
                uint32_t addr = stA + (wm*64 + mi*16 + (lane & 15))*ROWB + ((lane >> 4)*16 + ks*32);
                asm volatile("ldmatrix.sync.aligned.m8n8.x4.shared.b16 {%0,%1,%2,%3}, [%4];"
                    : "=r"(a[mi][0]), "=r"(a[mi][1]), "=r"(a[mi][2]), "=r"(a[mi][3]) : "r"(addr));
            }
            uint32_t b[4][2];
            #pragma unroll
            for (int ni = 0; ni < 4; ni++) {
                uint32_t addr = stB + (wn*32 + ni*8 + (lane & 7))*ROWB + (((lane >> 3) & 1)*16 + ks*32);
                asm volatile("ldmatrix.sync.aligned.m8n8.x2.shared.b16 {%0,%1}, [%2];"
                    : "=r"(b[ni][0]), "=r"(b[ni][1]) : "r"(addr));
            }
            #pragma unroll
            for (int mi = 0; mi < 4; mi++)
                #pragma unroll
                for (int ni = 0; ni < 4; ni++) {
                    asm volatile(
                        "mma.sync.aligned.m16n8k16.row.col.f32.bf16.bf16.f32 "
                        "{%0,%1,%2,%3}, {%4,%5,%6,%7}, {%8,%9}, {%0,%1,%2,%3};"
                        : "+f"(acc[mi][ni][0]), "+f"(acc[mi][ni][1]),
                          "+f"(acc[mi][ni][2]), "+f"(acc[mi][ni][3])
                        : "r"(a[mi][0]), "r"(a[mi][1]), "r"(a[mi][2]), "r"(a[mi][3]),
                          "r"(b[ni][0]), "r"(b[ni][1]));
                }
        }
    }

    // ---- epilogue ----
    const int g = lane >> 2, tig = lane & 3;
    #pragma unroll
    for (int mi = 0; mi < 4; mi++) {
        #pragma unroll
        for (int ni = 0; ni < 4; ni++) {
            int r0 = bm + wm*64 + mi*16 + g;
            int cc = bn + wn*32 + ni*8 + tig*2;
            #pragma unroll
            for (int half = 0; half < 2; half++) {
                int r = r0 + half*8;
                float v0 = acc[mi][ni][half*2 + 0];
                float v1 = acc[mi][ni][half*2 + 1];
                if (epi == 0) {
                    float2 st; st.x = v0; st.y = v1;
                    *(float2*)&C[(size_t)r*N + cc] = st;
                } else if (epi == 1) {
                    float2 bi  = *(const float2*)&bias[cc];
                    float2 res = *(const float2*)&C[(size_t)r*N + cc];
                    float2 st; st.x = v0 + bi.x + res.x; st.y = v1 + bi.y + res.y;
                    *(float2*)&C[(size_t)r*N + cc] = st;
                } else {
                    float2 bi = *(const float2*)&bias[cc];
                    float g0 = gelu_exact(v0 + bi.x);
                    float g1 = gelu_exact(v1 + bi.y);
                    __nv_bfloat16 h0,h1,l0,l1;
                    split_bf16(g0, h0, l0); split_bf16(g1, h1, l1);
                    __nv_bfloat162 sh; sh.x = h0; sh.y = h1;
                    __nv_bfloat162 sl; sl.x = l0; sl.y = l1;
                    *(__nv_bfloat162*)&O[(size_t)r*2*N + cc]     = sh;
                    *(__nv_bfloat162*)&O[(size_t)r*2*N + N + cc] = sl;
                }
            }
        }
    }
}

// ================= Host driver =================
extern "C" void kernel_launch(void* const* d_in, const int* in_sizes, int n_in,
                              void* d_out, int out_size) {
    const float* local_t  = (const float*)d_in[0];
    const float* region_t = (const float*)d_in[1];
    const float* emb      = (const float*)d_in[2];
    const float* attn_g   = (const float*)d_in[3];
    const float* attn_b   = (const float*)d_in[4];
    const float* wqkv     = (const float*)d_in[5];
    const float* wout     = (const float*)d_in[6];
    const float* bout     = (const float*)d_in[7];
    const float* mlp_g    = (const float*)d_in[8];
    const float* mlp_b    = (const float*)d_in[9];
    const float* w1       = (const float*)d_in[10];
    const float* b1       = (const float*)d_in[11];
    const float* w2       = (const float*)d_in[12];
    const float* b2       = (const float*)d_in[13];
    float* out = (float*)d_out;

    cudaFuncSetAttribute(gemm_mma, cudaFuncAttributeMaxDynamicSharedMemorySize, SMEM_GEMM);

    float *xw, *qkv, *biasT, *xr, *qkvr;
    __nv_bfloat16 *h, *o, *m1, *hr, *orr;
    __nv_bfloat16 *Wqkv, *Wout, *W1, *W2;
    cudaGetSymbolAddress((void**)&xw,   g_xw);
    cudaGetSymbolAddress((void**)&h,    g_h);
    cudaGetSymbolAddress((void**)&qkv,  g_qkv);
    cudaGetSymbolAddress((void**)&o,    g_o);
    cudaGetSymbolAddress((void**)&m1,   g_m1);
    cudaGetSymbolAddress((void**)&biasT,g_bias);
    cudaGetSymbolAddress((void**)&xr,   g_xr);
    cudaGetSymbolAddress((void**)&hr,   g_hr);
    cudaGetSymbolAddress((void**)&qkvr, g_qkvr);
    cudaGetSymbolAddress((void**)&orr,  g_or);
    cudaGetSymbolAddress((void**)&Wqkv, g_Wqkv);
    cudaGetSymbolAddress((void**)&Wout, g_Wout);
    cudaGetSymbolAddress((void**)&W1,   g_W1);
    cudaGetSymbolAddress((void**)&W2,   g_W2);

    pack_kernel<<<(NROWS*DIMV + 255)/256, 256>>>(local_t, region_t);
    bias_kernel<<<(HEADS*NTOK*NTOK + 255)/256, 256>>>(emb);

    for (int l = 0; l < DEPTH; l++) {
        wsplit<<<(DIMV*3*DIMV + 255)/256, 256>>>(wqkv + (size_t)l*DIMV*3*DIMV,
            Wqkv + (size_t)l*3*DIMV*2*DIMV, DIMV, 3*DIMV);
        wsplit<<<(DIMV*DIMV + 255)/256, 256>>>(wout + (size_t)l*DIMV*DIMV,
            Wout + (size_t)l*DIMV*2*DIMV, DIMV, DIMV);
        wsplit<<<(DIMV*4*DIMV + 255)/256, 256>>>(w1 + (size_t)l*DIMV*4*DIMV,
            W1 + (size_t)l*4*DIMV*2*DIMV, DIMV, 4*DIMV);
        wsplit<<<(4*DIMV*DIMV + 255)/256, 256>>>(w2 + (size_t)l*4*DIMV*DIMV,
            W2 + (size_t)l*DIMV*2*4*DIMV, 4*DIMV, DIMV);
    }

    for (int l = 0; l < DEPTH; l++) {
        __nv_bfloat16* WqT = Wqkv + (size_t)l*3*DIMV*2*DIMV;
        __nv_bfloat16* WoT = Wout + (size_t)l*DIMV*2*DIMV;
        __nv_bfloat16* W1T = W1   + (size_t)l*4*DIMV*2*DIMV;
        __nv_bfloat16* W2T = W2   + (size_t)l*DIMV*2*4*DIMV;
        const float* Bout = bout + (size_t)l*DIMV;
        const float* B1   = b1   + (size_t)l*4*DIMV;
        const float* B2   = b2   + (size_t)l*DIMV;
        const float* Ag   = attn_g + (size_t)l*DIMV;
        const float* Ab   = attn_b + (size_t)l*DIMV;
        const float* Mg   = mlp_g  + (size_t)l*DIMV;
        const float* Mb   = mlp_b  + (size_t)l*DIMV;

        // ---- region self-attention ----
        gather_region<<<(NWIN*DIMV + 255)/256, 256>>>();
        ln_kernel<<<NWIN, 128>>>(xr, Ag, Ab, hr);
        gemm_mma<<<dim3(3*DIMV/BN, NWIN/BM), 256, SMEM_GEMM>>>(hr, WqT, nullptr, qkvr, nullptr, 3*DIMV, DIMV, 0);
        attn_kernel<64><<<dim3(NB, HEADS), 256>>>(qkvr, nullptr, orr);
        gemm_mma<<<dim3(DIMV/BN, NWIN/BM), 256, SMEM_GEMM>>>(orr, WoT, Bout, xr, nullptr, DIMV, DIMV, 1);
        scatter_region<<<(NWIN*DIMV + 255)/256, 256>>>();

        // ---- window attention ----
        ln_kernel<<<NROWS, 128>>>(xw, Ag, Ab, h);
        gemm_mma<<<dim3(3*DIMV/BN, NROWS/BM), 256, SMEM_GEMM>>>(h, WqT, nullptr, qkv, nullptr, 3*DIMV, DIMV, 0);
        attn_kernel<NTOK><<<dim3(NWIN, HEADS), 256>>>(qkv, biasT, o);
        gemm_mma<<<dim3(DIMV/BN, NROWS/BM), 256, SMEM_GEMM>>>(o, WoT, Bout, xw, nullptr, DIMV, DIMV, 1);

        // ---- MLP ----
        ln_kernel<<<NROWS, 128>>>(xw, Mg, Mb, h);
        gemm_mma<<<dim3(4*DIMV/BN, NROWS/BM), 256, SMEM_GEMM>>>(h, W1T, B1, nullptr, m1, 4*DIMV, DIMV, 2);
        gemm_mma<<<dim3(DIMV/BN, NROWS/BM), 256, SMEM_GEMM>>>(m1, W2T, B2, xw, nullptr, DIMV, 4*DIMV, 1);
    }

    unpack_kernel<<<(NROWS*DIMV + 255)/256, 256>>>(out);
}